// round 10
// baseline (speedup 1.0000x reference)
#include <cuda_runtime.h>
#include <cuda_fp16.h>
#include <math.h>

#define BATCH 16
#define CCH   256
#define SP    1024
#define NHEAD 8
#define HDIM  32
#define NGRP  16
#define EPSV  1e-5f

// Scratch (static __device__ arrays — no allocation allowed)
__device__ __half g_norm_h[2][BATCH * CCH * SP];      // fp16 (GEMM input + residual)
__device__ __half g_qkv_h [2][BATCH * 3 * CCH * SP];  // fp16
__device__ __half g_attn_h[2][BATCH * CCH * SP];      // fp16
__device__ __half g_w_h   [2 * 768 * 256 + 2 * 256 * 256]; // converted weights

__device__ __forceinline__ unsigned pf2(float a, float b) {
    __half2 h = __floats2half2_rn(a, b);
    return *reinterpret_cast<unsigned*>(&h);
}
__device__ __forceinline__ unsigned hex2(unsigned x) {
    unsigned r;
    asm("ex2.approx.f16x2 %0, %1;" : "=r"(r) : "r"(x));
    return r;
}

__device__ __forceinline__ void mma16(float* c, const unsigned* a, const unsigned* b) {
    asm volatile(
        "mma.sync.aligned.m16n8k16.row.col.f32.f16.f16.f32 "
        "{%0,%1,%2,%3},{%4,%5,%6,%7},{%8,%9},{%0,%1,%2,%3};"
        : "+f"(c[0]), "+f"(c[1]), "+f"(c[2]), "+f"(c[3])
        : "r"(a[0]), "r"(a[1]), "r"(a[2]), "r"(a[3]), "r"(b[0]), "r"(b[1]));
}

__device__ __forceinline__ unsigned su32(const void* p) {
    return (unsigned)__cvta_generic_to_shared(p);
}
__device__ __forceinline__ void cp16(unsigned dst, const void* src) {
    asm volatile("cp.async.ca.shared.global [%0], [%1], 16;" :: "r"(dst), "l"(src));
}
__device__ __forceinline__ void cp_commit() {
    asm volatile("cp.async.commit_group;");
}
template<int N> __device__ __forceinline__ void cp_wait() {
    asm volatile("cp.async.wait_group %0;" :: "n"(N));
}
__device__ __forceinline__ void ldsm4(unsigned* r, unsigned a) {
    asm volatile("ldmatrix.sync.aligned.m8n8.x4.shared.b16 {%0,%1,%2,%3}, [%4];"
        : "=r"(r[0]), "=r"(r[1]), "=r"(r[2]), "=r"(r[3]) : "r"(a));
}
__device__ __forceinline__ void ldsm4t(unsigned* r, unsigned a) {
    asm volatile("ldmatrix.sync.aligned.m8n8.x4.trans.shared.b16 {%0,%1,%2,%3}, [%4];"
        : "=r"(r[0]), "=r"(r[1]), "=r"(r[2]), "=r"(r[3]) : "r"(a));
}

// ---------------------------------------------------------------------------
// GroupNorm + weight conversion in ONE launch.
// Blocks [0,512): GroupNorm both branches. Blocks [512,768): w2h conversion.
// ---------------------------------------------------------------------------
__global__ void __launch_bounds__(256) gn_w2h_kernel(
    const float* __restrict__ x0, const float* __restrict__ x1,
    const float* __restrict__ ga0, const float* __restrict__ ga1,
    const float* __restrict__ be0, const float* __restrict__ be1,
    __half* __restrict__ outHBase,
    const float* __restrict__ wqa, const float* __restrict__ wqb,
    const float* __restrict__ woa, const float* __restrict__ wob,
    __half* __restrict__ wOut)
{
    int tid = threadIdx.x;
    if (blockIdx.x >= 512) {
        // ---- weight conversion ----
        int t = (blockIdx.x - 512) * 256 + tid;
        size_t e = (size_t)t * 8;
        const float* src; size_t off;
        if      (e < 196608) { src = wqa; off = e; }
        else if (e < 393216) { src = wqb; off = e - 196608; }
        else if (e < 458752) { src = woa; off = e - 393216; }
        else                 { src = wob; off = e - 458752; }
        float4 v0 = *(const float4*)(src + off);
        float4 v1 = *(const float4*)(src + off + 4);
        unsigned r[4];
        r[0] = pf2(v0.x, v0.y); r[1] = pf2(v0.z, v0.w);
        r[2] = pf2(v1.x, v1.y); r[3] = pf2(v1.z, v1.w);
        *(uint4*)(wOut + e) = *(uint4*)r;
        return;
    }

    // ---- GroupNorm ----
    const int CPG = CCH / NGRP;      // 16
    const int n   = CPG * SP;        // 16384
    int bg = blockIdx.x;
    int br = bg >> 8; bg &= 255;
    const float* x     = br ? x1  : x0;
    const float* gamma = br ? ga1 : ga0;
    const float* beta  = br ? be1 : be0;
    const size_t NCS = (size_t)BATCH * CCH * SP;
    __half* out_h = outHBase + (size_t)br * NCS;

    int b = bg / NGRP, g = bg % NGRP;
    size_t base = (size_t)(b * CCH + g * CPG) * SP;
    const float* xp = x + base;

    float s = 0.f, s2 = 0.f;
    #pragma unroll 4
    for (int it = 0; it < n / 1024; it++) {
        float4 v = *(const float4*)&xp[(it * 256 + tid) * 4];
        s  += v.x + v.y + v.z + v.w;
        s2 += v.x * v.x + v.y * v.y + v.z * v.z + v.w * v.w;
    }
    __shared__ float rs[256], rq[256];
    rs[tid] = s; rq[tid] = s2;
    __syncthreads();
    for (int off = 128; off > 0; off >>= 1) {
        if (tid < off) { rs[tid] += rs[tid + off]; rq[tid] += rq[tid + off]; }
        __syncthreads();
    }
    float mean = rs[0] * (1.0f / n);
    float var  = rq[0] * (1.0f / n) - mean * mean;
    float inv  = rsqrtf(var + EPSV);

    #pragma unroll 4
    for (int it = 0; it < n / 1024; it++) {
        int e = (it * 256 + tid) * 4;
        int c = g * CPG + (e >> 10);
        float gm = gamma[c] * inv;
        float bt = beta[c] - mean * gm;
        float4 v = *(const float4*)&xp[e];
        unsigned r[2];
        r[0] = pf2(v.x * gm + bt, v.y * gm + bt);
        r[1] = pf2(v.z * gm + bt, v.w * gm + bt);
        *(uint2*)&out_h[base + e] = *(uint2*)r;
    }
}

// ---------------------------------------------------------------------------
// fp16 tensor-core GEMM, both branches per launch (grid.z = 32).
// BK=64 (4 k-iterations, 4 ks-steps each), 2-stage cp.async, dynamic smem.
// ---------------------------------------------------------------------------
#define WP 72    // halves; 144B row stride -> conflict-free ldmatrix
#define XP 136   // halves; 272B row stride -> conflict-free ldmatrix
#define STG_H (128 * WP + 64 * XP)          // halves per stage: 17920
#define GEMM_SMEM (2 * STG_H * 2)           // bytes: 71680

template<int HALF_OUT>
__global__ void __launch_bounds__(256) gemm16_kernel(
    const __half* __restrict__ W0, const __half* __restrict__ W1,
    const __half* __restrict__ X0, const __half* __restrict__ X1,
    void* __restrict__ Y0, void* __restrict__ Y1,
    const float* __restrict__ bias0, const float* __restrict__ bias1,
    const __half* __restrict__ resid0, const __half* __restrict__ resid1,
    int M)
{
    extern __shared__ __half sm[];

    int z = blockIdx.z;
    int br = z >> 4, b = z & 15;
    const __half* W = br ? W1 : W0;
    const __half* Xb = (br ? X1 : X0) + (size_t)b * CCH * SP;
    void* Y = br ? Y1 : Y0;
    const float* bias = br ? bias1 : bias0;
    const __half* resid = br ? resid1 : resid0;

    int m0 = blockIdx.y * 128, n0 = blockIdx.x * 128;

    int tid = threadIdx.x;
    int w = tid >> 5, lane = tid & 31;
    int gid = lane >> 2, tg = lane & 3;
    int wm = (w >> 1) * 32;
    int wn = (w & 1) * 64;

    float acc[2][8][4];
    #pragma unroll
    for (int i = 0; i < 2; i++)
        #pragma unroll
        for (int j = 0; j < 8; j++)
            #pragma unroll
            for (int k = 0; k < 4; k++) acc[i][j][k] = 0.f;

    // fill coords (BK=64)
    int wrow = tid >> 1;              // W row 0..127
    int wco  = (tid & 1) * 32;        // half-offset within row (2 thr x 32 halves)
    int xrow = tid >> 2;              // X row 0..63
    int xco  = (tid & 3) * 32;        // half-offset within row (4 thr x 32 halves)

    int la15 = lane & 15;
    int la16 = (lane >> 4) << 3;

    auto load_tile = [&](int kt, int buf) {
        __half* Ws = sm + buf * STG_H;
        __half* Xs = Ws + 128 * WP;
        const __half* wp = W + (size_t)(m0 + wrow) * CCH + kt * 64 + wco;
        unsigned wd = su32(&Ws[wrow * WP + wco]);
        cp16(wd,      wp);
        cp16(wd + 16, wp + 8);
        cp16(wd + 32, wp + 16);
        cp16(wd + 48, wp + 24);
        const __half* xp = Xb + (size_t)(kt * 64 + xrow) * SP + n0 + xco;
        unsigned xd = su32(&Xs[xrow * XP + xco]);
        cp16(xd,      xp);
        cp16(xd + 16, xp + 8);
        cp16(xd + 32, xp + 16);
        cp16(xd + 48, xp + 24);
    };

    load_tile(0, 0);
    cp_commit();

    for (int kt = 0; kt < 4; kt++) {
        int cur = kt & 1;
        cp_wait<0>();
        __syncthreads();
        if (kt < 3) { load_tile(kt + 1, cur ^ 1); cp_commit(); }
        __half* Ws = sm + cur * STG_H;
        __half* Xs = Ws + 128 * WP;

        #pragma unroll
        for (int ks = 0; ks < 4; ks++) {
            int kh = 16 * ks;
            unsigned af[2][4], bf[8][2];
            #pragma unroll
            for (int mt = 0; mt < 2; mt++) {
                unsigned a = su32(&Ws[(wm + 16 * mt + la15) * WP + kh + la16]);
                ldsm4(af[mt], a);
            }
            #pragma unroll
            for (int nfp = 0; nfp < 4; nfp++) {
                unsigned r[4];
                unsigned a = su32(&Xs[(kh + la15) * XP + wn + 16 * nfp + la16]);
                ldsm4t(r, a);
                bf[2 * nfp][0] = r[0]; bf[2 * nfp][1] = r[1];
                bf[2 * nfp + 1][0] = r[2]; bf[2 * nfp + 1][1] = r[3];
            }
            #pragma unroll
            for (int mt = 0; mt < 2; mt++)
                #pragma unroll
                for (int nt = 0; nt < 8; nt++)
                    mma16(acc[mt][nt], af[mt], bf[nt]);
        }
    }

    // Epilogue
    #pragma unroll
    for (int mt = 0; mt < 2; mt++) {
        int m = m0 + wm + 16 * mt + gid;
        #pragma unroll
        for (int nt = 0; nt < 8; nt++) {
            int n = n0 + wn + 8 * nt + 2 * tg;
            if (HALF_OUT) {
                __half* Yb = (__half*)Y + (size_t)b * M * SP;
                *(unsigned*)&Yb[(size_t)m * SP + n] =
                    pf2(acc[mt][nt][0], acc[mt][nt][1]);
                *(unsigned*)&Yb[(size_t)(m + 8) * SP + n] =
                    pf2(acc[mt][nt][2], acc[mt][nt][3]);
            } else {
                float* Yb = (float*)Y + (size_t)b * M * SP;
                const __half* Rb = resid + (size_t)b * CCH * SP;
                float bv0 = bias[m], bv1 = bias[m + 8];
                __half2 r0 = *(const __half2*)&Rb[(size_t)m * SP + n];
                __half2 r1 = *(const __half2*)&Rb[(size_t)(m + 8) * SP + n];
                float2 f0 = __half22float2(r0);
                float2 f1 = __half22float2(r1);
                float2 o0, o1;
                o0.x = acc[mt][nt][0] + bv0 + f0.x;
                o0.y = acc[mt][nt][1] + bv0 + f0.y;
                o1.x = acc[mt][nt][2] + bv1 + f1.x;
                o1.y = acc[mt][nt][3] + bv1 + f1.y;
                *(float2*)&Yb[(size_t)m * SP + n] = o0;
                *(float2*)&Yb[(size_t)(m + 8) * SP + n] = o1;
            }
        }
    }
}

// ---------------------------------------------------------------------------
// Flash attention, fp16 mma. 8 warps x 32 queries = 256 queries per block.
// Two m16 tiles per warp amortize every K/V B-fragment ldmatrix over 2x mma.
// 16-key chunks; no max-tracking; exp2 fp16x2; l via ones-mma (tensor pipe).
// ---------------------------------------------------------------------------
#define AKP 136   // halves; 272B row stride -> conflict-free ldmatrix
#define ONES2 0x3C003C00u

__global__ void __launch_bounds__(256) attn16_kernel(
    const __half* __restrict__ qkvA, const __half* __restrict__ qkvB,
    __half* __restrict__ attnBase)   // [2][B,256,S] fp16
{
    __shared__ __half Ks[2][32 * AKP];
    __shared__ __half Vs[2][32 * AKP];

    int bx = blockIdx.x;
    int br = bx >> 7;                // 0: attnA (Q from B, KV from A)
    int bh = bx & 127;
    int b = bh >> 3, h = bh & 7;
    int qi0 = blockIdx.y * 256;

    const size_t NCS = (size_t)BATCH * CCH * SP;
    const __half* qkvQ  = br ? qkvA : qkvB;
    const __half* qkvKV = br ? qkvB : qkvA;
    const __half* qp = qkvQ  + (size_t)(b * 768 + h * 96) * SP;
    const __half* kp = qkvKV + (size_t)(b * 768 + h * 96 + 32) * SP;
    const __half* vp = qkvKV + (size_t)(b * 768 + h * 96 + 64) * SP;
    __half*       op = attnBase + (size_t)br * NCS + (size_t)(b * CCH + h * HDIM) * SP;

    int tid = threadIdx.x;
    int w = tid >> 5, lane = tid & 31;
    int gid = lane >> 2, tg = lane & 3;
    int qrow0 = qi0 + w * 32 + gid;       // m-tile 0; m-tile 1 at +16

    int la15 = lane & 15;
    int la16 = (lane >> 4) << 3;
    int la8  = lane & 8;
    int la7  = lane & 7;

    // Q fragments for two m16 tiles, scaled by log2(e)/16 in fp32
    const float QS = 0.090168441f;   // log2(e)/16
    unsigned qa[2][2][4];            // [m-tile][kf][frag]
    #pragma unroll
    for (int mt = 0; mt < 2; mt++) {
        int qr = qrow0 + 16 * mt;
        #pragma unroll
        for (int kf = 0; kf < 2; kf++) {
            int c0 = 16 * kf + 2 * tg;
            qa[mt][kf][0] = pf2(__half2float(qp[(size_t)c0 * SP + qr]) * QS,
                                __half2float(qp[(size_t)(c0 + 1) * SP + qr]) * QS);
            qa[mt][kf][1] = pf2(__half2float(qp[(size_t)c0 * SP + qr + 8]) * QS,
                                __half2float(qp[(size_t)(c0 + 1) * SP + qr + 8]) * QS);
            qa[mt][kf][2] = pf2(__half2float(qp[(size_t)(c0 + 8) * SP + qr]) * QS,
                                __half2float(qp[(size_t)(c0 + 9) * SP + qr]) * QS);
            qa[mt][kf][3] = pf2(__half2float(qp[(size_t)(c0 + 8) * SP + qr + 8]) * QS,
                                __half2float(qp[(size_t)(c0 + 9) * SP + qr + 8]) * QS);
        }
    }

    float o[2][4][4];                 // [m-tile][n-frag][4]
    #pragma unroll
    for (int mt = 0; mt < 2; mt++)
        #pragma unroll
        for (int i = 0; i < 4; i++)
            #pragma unroll
            for (int j = 0; j < 4; j++) o[mt][i][j] = 0.f;
    float lacc[2][4] = {{0.f,0.f,0.f,0.f},{0.f,0.f,0.f,0.f}};
    const unsigned onesb[2] = {ONES2, ONES2};

    // fill: 32 ch x 128 keys per tensor = 512 16B-chunks; 256 thr x 2 each
    auto load_kv = [&](int jt, int buf) {
        #pragma unroll
        for (int u = 0; u < 2; u++) {
            int cid = 2 * tid + u;            // 0..511
            int row = cid >> 4, c = cid & 15;
            const __half* ksrc = kp + (size_t)row * SP + jt * 128 + c * 8;
            const __half* vsrc = vp + (size_t)row * SP + jt * 128 + c * 8;
            cp16(su32(&Ks[buf][row * AKP + c * 8]), ksrc);
            cp16(su32(&Vs[buf][row * AKP + c * 8]), vsrc);
        }
    };

    load_kv(0, 0);
    cp_commit();

    for (int jt = 0; jt < 8; jt++) {
        int cur = jt & 1;
        cp_wait<0>();
        __syncthreads();
        if (jt < 7) { load_kv(jt + 1, cur ^ 1); cp_commit(); }

        // Process the 128-key tile in 16-key chunks; each chunk's K/V
        // ldmatrix serves BOTH m-tiles.
        #pragma unroll
        for (int nc = 0; nc < 8; nc++) {
            // S = Q K^T for 16 keys (2 n-frags) x 2 m-tiles
            float s[2][2][4];
            #pragma unroll
            for (int mt = 0; mt < 2; mt++)
                #pragma unroll
                for (int nf = 0; nf < 2; nf++)
                    #pragma unroll
                    for (int j = 0; j < 4; j++) s[mt][nf][j] = 0.f;
            #pragma unroll
            for (int kf = 0; kf < 2; kf++) {
                unsigned r[4];
                unsigned a = su32(&Ks[cur][(16 * kf + la15) * AKP + 16 * nc + la16]);
                ldsm4t(r, a);
                #pragma unroll
                for (int mt = 0; mt < 2; mt++) {
                    mma16(s[mt][0], qa[mt][kf], r);
                    mma16(s[mt][1], qa[mt][kf], r + 2);
                }
            }

            // P = exp2(S) -> A-fragment; l += P*1 (tensor); O += P V^T
            unsigned pa[2][4];
            #pragma unroll
            for (int mt = 0; mt < 2; mt++) {
                pa[mt][0] = hex2(pf2(s[mt][0][0], s[mt][0][1]));
                pa[mt][1] = hex2(pf2(s[mt][0][2], s[mt][0][3]));
                pa[mt][2] = hex2(pf2(s[mt][1][0], s[mt][1][1]));
                pa[mt][3] = hex2(pf2(s[mt][1][2], s[mt][1][3]));
                mma16(lacc[mt], pa[mt], onesb);
            }
            #pragma unroll
            for (int np = 0; np < 2; np++) {
                unsigned r[4];
                unsigned a = su32(&Vs[cur][(16 * np + la16 + la7) * AKP
                                           + 16 * nc + la8]);
                ldsm4(r, a);
                #pragma unroll
                for (int mt = 0; mt < 2; mt++) {
                    mma16(o[mt][2 * np],     pa[mt], r);
                    mma16(o[mt][2 * np + 1], pa[mt], r + 2);
                }
            }
        }
    }

    #pragma unroll
    for (int mt = 0; mt < 2; mt++) {
        int qr = qrow0 + 16 * mt;
        float il0 = 1.0f / lacc[mt][0], il1 = 1.0f / lacc[mt][2];
        #pragma unroll
        for (int nf2 = 0; nf2 < 4; nf2++) {
            int c = 8 * nf2 + 2 * tg;
            op[(size_t)c * SP + qr]           = __float2half(o[mt][nf2][0] * il0);
            op[(size_t)(c + 1) * SP + qr]     = __float2half(o[mt][nf2][1] * il0);
            op[(size_t)c * SP + qr + 8]       = __float2half(o[mt][nf2][2] * il1);
            op[(size_t)(c + 1) * SP + qr + 8] = __float2half(o[mt][nf2][3] * il1);
        }
    }
}

// ---------------------------------------------------------------------------
extern "C" void kernel_launch(void* const* d_in, const int* in_sizes, int n_in,
                              void* d_out, int out_size)
{
    const float* x_A   = (const float*)d_in[0];
    const float* x_B   = (const float*)d_in[1];
    const float* gA    = (const float*)d_in[2];
    const float* bA    = (const float*)d_in[3];
    const float* gB    = (const float*)d_in[4];
    const float* bB    = (const float*)d_in[5];
    const float* WqkvA = (const float*)d_in[6];
    const float* WqkvB = (const float*)d_in[7];
    const float* WoutA = (const float*)d_in[8];
    const float* boutA = (const float*)d_in[9];
    const float* WoutB = (const float*)d_in[10];
    const float* boutB = (const float*)d_in[11];
    float* outp = (float*)d_out;

    __half *normHBase, *qkvBase, *attnBase, *whBase;
    cudaGetSymbolAddress((void**)&normHBase, g_norm_h);
    cudaGetSymbolAddress((void**)&qkvBase,   g_qkv_h);
    cudaGetSymbolAddress((void**)&attnBase,  g_attn_h);
    cudaGetSymbolAddress((void**)&whBase,    g_w_h);

    cudaFuncSetAttribute(gemm16_kernel<1>,
        cudaFuncAttributeMaxDynamicSharedMemorySize, GEMM_SMEM);
    cudaFuncSetAttribute(gemm16_kernel<0>,
        cudaFuncAttributeMaxDynamicSharedMemorySize, GEMM_SMEM);

    const size_t NCS  = (size_t)BATCH * CCH * SP;
    const size_t NQKV = (size_t)BATCH * 3 * CCH * SP;
    __half* normAh = normHBase;
    __half* normBh = normHBase + NCS;
    __half* qkvA   = qkvBase;
    __half* qkvB   = qkvBase + NQKV;
    __half* attnA  = attnBase;
    __half* attnB  = attnBase + NCS;
    __half* wqaH = whBase;
    __half* wqbH = whBase + 196608;
    __half* woaH = whBase + 393216;
    __half* wobH = whBase + 458752;

    // 1) GroupNorm (both branches) + weight conversion, one launch
    gn_w2h_kernel<<<768, 256>>>(
        x_A, x_B, gA, gB, bA, bB, normHBase,
        WqkvA, WqkvB, WoutA, WoutB, whBase);

    // 2) QKV projections, both branches (M = 768), BK=64
    dim3 gq(SP / 128, 768 / 128, 32);
    gemm16_kernel<1><<<gq, 256, GEMM_SMEM>>>(wqaH, wqbH, normAh, normBh,
                                  qkvA, qkvB, nullptr, nullptr,
                                  nullptr, nullptr, 768);

    // 3) Cross attention, both branches (256 queries per block)
    dim3 ga(2 * BATCH * NHEAD, SP / 256);
    attn16_kernel<<<ga, 256>>>(qkvA, qkvB, attnBase);

    // 4) Output projection + bias + fp16 residual, both branches (M = 256)
    dim3 go(SP / 128, 256 / 128, 32);
    gemm16_kernel<0><<<go, 256, GEMM_SMEM>>>(woaH, wobH, attnA, attnB,
                                  outp, outp + NCS, boutA, boutB,
                                  normAh, normBh, 256);
}

// round 11
// speedup vs baseline: 1.0424x; 1.0424x over previous
#include <cuda_runtime.h>
#include <cuda_fp16.h>
#include <math.h>

#define BATCH 16
#define CCH   256
#define SP    1024
#define NHEAD 8
#define HDIM  32
#define NGRP  16
#define EPSV  1e-5f

// Scratch (static __device__ arrays — no allocation allowed)
__device__ __half g_norm_h[2][BATCH * CCH * SP];      // fp16 (GEMM input + residual)
__device__ __half g_qkv_h [2][BATCH * 3 * CCH * SP];  // fp16
__device__ __half g_attn_h[2][BATCH * CCH * SP];      // fp16
__device__ __half g_w_h   [2 * 768 * 256 + 2 * 256 * 256]; // converted weights

__device__ __forceinline__ unsigned pf2(float a, float b) {
    __half2 h = __floats2half2_rn(a, b);
    return *reinterpret_cast<unsigned*>(&h);
}
__device__ __forceinline__ unsigned hex2(unsigned x) {
    unsigned r;
    asm("ex2.approx.f16x2 %0, %1;" : "=r"(r) : "r"(x));
    return r;
}

__device__ __forceinline__ void mma16(float* c, const unsigned* a, const unsigned* b) {
    asm volatile(
        "mma.sync.aligned.m16n8k16.row.col.f32.f16.f16.f32 "
        "{%0,%1,%2,%3},{%4,%5,%6,%7},{%8,%9},{%0,%1,%2,%3};"
        : "+f"(c[0]), "+f"(c[1]), "+f"(c[2]), "+f"(c[3])
        : "r"(a[0]), "r"(a[1]), "r"(a[2]), "r"(a[3]), "r"(b[0]), "r"(b[1]));
}

__device__ __forceinline__ unsigned su32(const void* p) {
    return (unsigned)__cvta_generic_to_shared(p);
}
__device__ __forceinline__ void cp16(unsigned dst, const void* src) {
    asm volatile("cp.async.ca.shared.global [%0], [%1], 16;" :: "r"(dst), "l"(src));
}
__device__ __forceinline__ void cp_commit() {
    asm volatile("cp.async.commit_group;");
}
template<int N> __device__ __forceinline__ void cp_wait() {
    asm volatile("cp.async.wait_group %0;" :: "n"(N));
}
__device__ __forceinline__ void ldsm4(unsigned* r, unsigned a) {
    asm volatile("ldmatrix.sync.aligned.m8n8.x4.shared.b16 {%0,%1,%2,%3}, [%4];"
        : "=r"(r[0]), "=r"(r[1]), "=r"(r[2]), "=r"(r[3]) : "r"(a));
}
__device__ __forceinline__ void ldsm4t(unsigned* r, unsigned a) {
    asm volatile("ldmatrix.sync.aligned.m8n8.x4.trans.shared.b16 {%0,%1,%2,%3}, [%4];"
        : "=r"(r[0]), "=r"(r[1]), "=r"(r[2]), "=r"(r[3]) : "r"(a));
}

// ---------------------------------------------------------------------------
// GroupNorm + weight conversion in ONE launch.
// Blocks [0,512): GroupNorm both branches. Blocks [512,768): w2h conversion.
// ---------------------------------------------------------------------------
__global__ void __launch_bounds__(256) gn_w2h_kernel(
    const float* __restrict__ x0, const float* __restrict__ x1,
    const float* __restrict__ ga0, const float* __restrict__ ga1,
    const float* __restrict__ be0, const float* __restrict__ be1,
    __half* __restrict__ outHBase,
    const float* __restrict__ wqa, const float* __restrict__ wqb,
    const float* __restrict__ woa, const float* __restrict__ wob,
    __half* __restrict__ wOut)
{
    int tid = threadIdx.x;
    if (blockIdx.x >= 512) {
        // ---- weight conversion ----
        int t = (blockIdx.x - 512) * 256 + tid;
        size_t e = (size_t)t * 8;
        const float* src; size_t off;
        if      (e < 196608) { src = wqa; off = e; }
        else if (e < 393216) { src = wqb; off = e - 196608; }
        else if (e < 458752) { src = woa; off = e - 393216; }
        else                 { src = wob; off = e - 458752; }
        float4 v0 = *(const float4*)(src + off);
        float4 v1 = *(const float4*)(src + off + 4);
        unsigned r[4];
        r[0] = pf2(v0.x, v0.y); r[1] = pf2(v0.z, v0.w);
        r[2] = pf2(v1.x, v1.y); r[3] = pf2(v1.z, v1.w);
        *(uint4*)(wOut + e) = *(uint4*)r;
        return;
    }

    // ---- GroupNorm ----
    const int CPG = CCH / NGRP;      // 16
    const int n   = CPG * SP;        // 16384
    int bg = blockIdx.x;
    int br = bg >> 8; bg &= 255;
    const float* x     = br ? x1  : x0;
    const float* gamma = br ? ga1 : ga0;
    const float* beta  = br ? be1 : be0;
    const size_t NCS = (size_t)BATCH * CCH * SP;
    __half* out_h = outHBase + (size_t)br * NCS;

    int b = bg / NGRP, g = bg % NGRP;
    size_t base = (size_t)(b * CCH + g * CPG) * SP;
    const float* xp = x + base;

    float s = 0.f, s2 = 0.f;
    #pragma unroll 4
    for (int it = 0; it < n / 1024; it++) {
        float4 v = *(const float4*)&xp[(it * 256 + tid) * 4];
        s  += v.x + v.y + v.z + v.w;
        s2 += v.x * v.x + v.y * v.y + v.z * v.z + v.w * v.w;
    }
    __shared__ float rs[256], rq[256];
    rs[tid] = s; rq[tid] = s2;
    __syncthreads();
    for (int off = 128; off > 0; off >>= 1) {
        if (tid < off) { rs[tid] += rs[tid + off]; rq[tid] += rq[tid + off]; }
        __syncthreads();
    }
    float mean = rs[0] * (1.0f / n);
    float var  = rq[0] * (1.0f / n) - mean * mean;
    float inv  = rsqrtf(var + EPSV);

    #pragma unroll 4
    for (int it = 0; it < n / 1024; it++) {
        int e = (it * 256 + tid) * 4;
        int c = g * CPG + (e >> 10);
        float gm = gamma[c] * inv;
        float bt = beta[c] - mean * gm;
        float4 v = *(const float4*)&xp[e];
        unsigned r[2];
        r[0] = pf2(v.x * gm + bt, v.y * gm + bt);
        r[1] = pf2(v.z * gm + bt, v.w * gm + bt);
        *(uint2*)&out_h[base + e] = *(uint2*)r;
    }
}

// ---------------------------------------------------------------------------
// fp16 tensor-core GEMM, both branches per launch (grid.z = 32).
// BK=32, 3-stage cp.async pipeline; fp16 residual for the HALF_OUT=0 path.
// ---------------------------------------------------------------------------
#define WPITCH 40
#define XPITCH 136

template<int HALF_OUT>
__global__ void __launch_bounds__(256) gemm16_kernel(
    const __half* __restrict__ W0, const __half* __restrict__ W1,
    const __half* __restrict__ X0, const __half* __restrict__ X1,
    void* __restrict__ Y0, void* __restrict__ Y1,
    const float* __restrict__ bias0, const float* __restrict__ bias1,
    const __half* __restrict__ resid0, const __half* __restrict__ resid1,
    int M)
{
    __shared__ __half Ws[3][128 * WPITCH];
    __shared__ __half Xs[3][32 * XPITCH];

    int z = blockIdx.z;
    int br = z >> 4, b = z & 15;
    const __half* W = br ? W1 : W0;
    const __half* Xb = (br ? X1 : X0) + (size_t)b * CCH * SP;
    void* Y = br ? Y1 : Y0;
    const float* bias = br ? bias1 : bias0;
    const __half* resid = br ? resid1 : resid0;

    int m0 = blockIdx.y * 128, n0 = blockIdx.x * 128;

    int tid = threadIdx.x;
    int w = tid >> 5, lane = tid & 31;
    int gid = lane >> 2, tg = lane & 3;
    int wm = (w >> 1) * 32;
    int wn = (w & 1) * 64;

    float acc[2][8][4];
    #pragma unroll
    for (int i = 0; i < 2; i++)
        #pragma unroll
        for (int j = 0; j < 8; j++)
            #pragma unroll
            for (int k = 0; k < 4; k++) acc[i][j][k] = 0.f;

    int wrow = tid >> 1;
    int wch  = (tid & 1) * 2;
    int xrow = tid >> 3;
    int xch  = (tid & 7) * 2;

    int la15 = lane & 15;
    int la16 = (lane >> 4) << 3;

    auto load_tile = [&](int kt, int buf) {
        const __half* wp = W + (size_t)(m0 + wrow) * CCH + kt * 32 + wch * 8;
        unsigned wd = su32(&Ws[buf][wrow * WPITCH + wch * 8]);
        cp16(wd,      wp);
        cp16(wd + 16, wp + 8);
        const __half* xp = Xb + (size_t)(kt * 32 + xrow) * SP + n0 + xch * 8;
        unsigned xd = su32(&Xs[buf][xrow * XPITCH + xch * 8]);
        cp16(xd,      xp);
        cp16(xd + 16, xp + 8);
    };

    load_tile(0, 0); cp_commit();
    load_tile(1, 1); cp_commit();

    for (int kt = 0; kt < 8; kt++) {
        int cur = kt % 3;
        if (kt < 7) cp_wait<1>(); else cp_wait<0>();
        __syncthreads();
        if (kt + 2 < 8) { load_tile(kt + 2, (kt + 2) % 3); cp_commit(); }

        #pragma unroll
        for (int ks = 0; ks < 2; ks++) {
            int kh = 16 * ks;
            unsigned af[2][4], bf[8][2];
            #pragma unroll
            for (int mt = 0; mt < 2; mt++) {
                unsigned a = su32(&Ws[cur][(wm + 16 * mt + la15) * WPITCH + kh + la16]);
                ldsm4(af[mt], a);
            }
            #pragma unroll
            for (int nfp = 0; nfp < 4; nfp++) {
                unsigned r[4];
                unsigned a = su32(&Xs[cur][(kh + la15) * XPITCH + wn + 16 * nfp + la16]);
                ldsm4t(r, a);
                bf[2 * nfp][0] = r[0]; bf[2 * nfp][1] = r[1];
                bf[2 * nfp + 1][0] = r[2]; bf[2 * nfp + 1][1] = r[3];
            }
            #pragma unroll
            for (int mt = 0; mt < 2; mt++)
                #pragma unroll
                for (int nt = 0; nt < 8; nt++)
                    mma16(acc[mt][nt], af[mt], bf[nt]);
        }
    }

    // Epilogue
    #pragma unroll
    for (int mt = 0; mt < 2; mt++) {
        int m = m0 + wm + 16 * mt + gid;
        #pragma unroll
        for (int nt = 0; nt < 8; nt++) {
            int n = n0 + wn + 8 * nt + 2 * tg;
            if (HALF_OUT) {
                __half* Yb = (__half*)Y + (size_t)b * M * SP;
                *(unsigned*)&Yb[(size_t)m * SP + n] =
                    pf2(acc[mt][nt][0], acc[mt][nt][1]);
                *(unsigned*)&Yb[(size_t)(m + 8) * SP + n] =
                    pf2(acc[mt][nt][2], acc[mt][nt][3]);
            } else {
                float* Yb = (float*)Y + (size_t)b * M * SP;
                const __half* Rb = resid + (size_t)b * CCH * SP;
                float bv0 = bias[m], bv1 = bias[m + 8];
                __half2 r0 = *(const __half2*)&Rb[(size_t)m * SP + n];
                __half2 r1 = *(const __half2*)&Rb[(size_t)(m + 8) * SP + n];
                float2 f0 = __half22float2(r0);
                float2 f1 = __half22float2(r1);
                float2 o0, o1;
                o0.x = acc[mt][nt][0] + bv0 + f0.x;
                o0.y = acc[mt][nt][1] + bv0 + f0.y;
                o1.x = acc[mt][nt][2] + bv1 + f1.x;
                o1.y = acc[mt][nt][3] + bv1 + f1.y;
                *(float2*)&Yb[(size_t)m * SP + n] = o0;
                *(float2*)&Yb[(size_t)(m + 8) * SP + n] = o1;
            }
        }
    }
}

// ---------------------------------------------------------------------------
// Flash attention, fp16 mma. 8 warps x 32 queries = 256 queries per block.
// Two m16 tiles per warp amortize every K/V B-fragment ldmatrix over 2x mma.
// 16-key chunks; no max-tracking; exp2 fp16x2; l via ones-mma (tensor pipe).
// ---------------------------------------------------------------------------
#define AKP 136   // halves; 272B row stride -> conflict-free ldmatrix
#define ONES2 0x3C003C00u

__global__ void __launch_bounds__(256) attn16_kernel(
    const __half* __restrict__ qkvA, const __half* __restrict__ qkvB,
    __half* __restrict__ attnBase)   // [2][B,256,S] fp16
{
    __shared__ __half Ks[2][32 * AKP];
    __shared__ __half Vs[2][32 * AKP];

    int bx = blockIdx.x;
    int br = bx >> 7;                // 0: attnA (Q from B, KV from A)
    int bh = bx & 127;
    int b = bh >> 3, h = bh & 7;
    int qi0 = blockIdx.y * 256;

    const size_t NCS = (size_t)BATCH * CCH * SP;
    const __half* qkvQ  = br ? qkvA : qkvB;
    const __half* qkvKV = br ? qkvB : qkvA;
    const __half* qp = qkvQ  + (size_t)(b * 768 + h * 96) * SP;
    const __half* kp = qkvKV + (size_t)(b * 768 + h * 96 + 32) * SP;
    const __half* vp = qkvKV + (size_t)(b * 768 + h * 96 + 64) * SP;
    __half*       op = attnBase + (size_t)br * NCS + (size_t)(b * CCH + h * HDIM) * SP;

    int tid = threadIdx.x;
    int w = tid >> 5, lane = tid & 31;
    int gid = lane >> 2, tg = lane & 3;
    int qrow0 = qi0 + w * 32 + gid;       // m-tile 0; m-tile 1 at +16

    int la15 = lane & 15;
    int la16 = (lane >> 4) << 3;
    int la8  = lane & 8;
    int la7  = lane & 7;

    // Q fragments for two m16 tiles, scaled by log2(e)/16 in fp32
    const float QS = 0.090168441f;   // log2(e)/16
    unsigned qa[2][2][4];            // [m-tile][kf][frag]
    #pragma unroll
    for (int mt = 0; mt < 2; mt++) {
        int qr = qrow0 + 16 * mt;
        #pragma unroll
        for (int kf = 0; kf < 2; kf++) {
            int c0 = 16 * kf + 2 * tg;
            qa[mt][kf][0] = pf2(__half2float(qp[(size_t)c0 * SP + qr]) * QS,
                                __half2float(qp[(size_t)(c0 + 1) * SP + qr]) * QS);
            qa[mt][kf][1] = pf2(__half2float(qp[(size_t)c0 * SP + qr + 8]) * QS,
                                __half2float(qp[(size_t)(c0 + 1) * SP + qr + 8]) * QS);
            qa[mt][kf][2] = pf2(__half2float(qp[(size_t)(c0 + 8) * SP + qr]) * QS,
                                __half2float(qp[(size_t)(c0 + 9) * SP + qr]) * QS);
            qa[mt][kf][3] = pf2(__half2float(qp[(size_t)(c0 + 8) * SP + qr + 8]) * QS,
                                __half2float(qp[(size_t)(c0 + 9) * SP + qr + 8]) * QS);
        }
    }

    float o[2][4][4];                 // [m-tile][n-frag][4]
    #pragma unroll
    for (int mt = 0; mt < 2; mt++)
        #pragma unroll
        for (int i = 0; i < 4; i++)
            #pragma unroll
            for (int j = 0; j < 4; j++) o[mt][i][j] = 0.f;
    float lacc[2][4] = {{0.f,0.f,0.f,0.f},{0.f,0.f,0.f,0.f}};
    const unsigned onesb[2] = {ONES2, ONES2};

    // fill: 32 ch x 128 keys per tensor = 512 16B-chunks; 256 thr x 2 each
    auto load_kv = [&](int jt, int buf) {
        #pragma unroll
        for (int u = 0; u < 2; u++) {
            int cid = 2 * tid + u;            // 0..511
            int row = cid >> 4, c = cid & 15;
            const __half* ksrc = kp + (size_t)row * SP + jt * 128 + c * 8;
            const __half* vsrc = vp + (size_t)row * SP + jt * 128 + c * 8;
            cp16(su32(&Ks[buf][row * AKP + c * 8]), ksrc);
            cp16(su32(&Vs[buf][row * AKP + c * 8]), vsrc);
        }
    };

    load_kv(0, 0);
    cp_commit();

    for (int jt = 0; jt < 8; jt++) {
        int cur = jt & 1;
        cp_wait<0>();
        __syncthreads();
        if (jt < 7) { load_kv(jt + 1, cur ^ 1); cp_commit(); }

        // Process the 128-key tile in 16-key chunks; each chunk's K/V
        // ldmatrix serves BOTH m-tiles.
        #pragma unroll
        for (int nc = 0; nc < 8; nc++) {
            // S = Q K^T for 16 keys (2 n-frags) x 2 m-tiles
            float s[2][2][4];
            #pragma unroll
            for (int mt = 0; mt < 2; mt++)
                #pragma unroll
                for (int nf = 0; nf < 2; nf++)
                    #pragma unroll
                    for (int j = 0; j < 4; j++) s[mt][nf][j] = 0.f;
            #pragma unroll
            for (int kf = 0; kf < 2; kf++) {
                unsigned r[4];
                unsigned a = su32(&Ks[cur][(16 * kf + la15) * AKP + 16 * nc + la16]);
                ldsm4t(r, a);
                #pragma unroll
                for (int mt = 0; mt < 2; mt++) {
                    mma16(s[mt][0], qa[mt][kf], r);
                    mma16(s[mt][1], qa[mt][kf], r + 2);
                }
            }

            // P = exp2(S) -> A-fragment; l += P*1 (tensor); O += P V^T
            unsigned pa[2][4];
            #pragma unroll
            for (int mt = 0; mt < 2; mt++) {
                pa[mt][0] = hex2(pf2(s[mt][0][0], s[mt][0][1]));
                pa[mt][1] = hex2(pf2(s[mt][0][2], s[mt][0][3]));
                pa[mt][2] = hex2(pf2(s[mt][1][0], s[mt][1][1]));
                pa[mt][3] = hex2(pf2(s[mt][1][2], s[mt][1][3]));
                mma16(lacc[mt], pa[mt], onesb);
            }
            #pragma unroll
            for (int np = 0; np < 2; np++) {
                unsigned r[4];
                unsigned a = su32(&Vs[cur][(16 * np + la16 + la7) * AKP
                                           + 16 * nc + la8]);
                ldsm4(r, a);
                #pragma unroll
                for (int mt = 0; mt < 2; mt++) {
                    mma16(o[mt][2 * np],     pa[mt], r);
                    mma16(o[mt][2 * np + 1], pa[mt], r + 2);
                }
            }
        }
    }

    #pragma unroll
    for (int mt = 0; mt < 2; mt++) {
        int qr = qrow0 + 16 * mt;
        float il0 = 1.0f / lacc[mt][0], il1 = 1.0f / lacc[mt][2];
        #pragma unroll
        for (int nf2 = 0; nf2 < 4; nf2++) {
            int c = 8 * nf2 + 2 * tg;
            op[(size_t)c * SP + qr]           = __float2half(o[mt][nf2][0] * il0);
            op[(size_t)(c + 1) * SP + qr]     = __float2half(o[mt][nf2][1] * il0);
            op[(size_t)c * SP + qr + 8]       = __float2half(o[mt][nf2][2] * il1);
            op[(size_t)(c + 1) * SP + qr + 8] = __float2half(o[mt][nf2][3] * il1);
        }
    }
}

// ---------------------------------------------------------------------------
extern "C" void kernel_launch(void* const* d_in, const int* in_sizes, int n_in,
                              void* d_out, int out_size)
{
    const float* x_A   = (const float*)d_in[0];
    const float* x_B   = (const float*)d_in[1];
    const float* gA    = (const float*)d_in[2];
    const float* bA    = (const float*)d_in[3];
    const float* gB    = (const float*)d_in[4];
    const float* bB    = (const float*)d_in[5];
    const float* WqkvA = (const float*)d_in[6];
    const float* WqkvB = (const float*)d_in[7];
    const float* WoutA = (const float*)d_in[8];
    const float* boutA = (const float*)d_in[9];
    const float* WoutB = (const float*)d_in[10];
    const float* boutB = (const float*)d_in[11];
    float* outp = (float*)d_out;

    __half *normHBase, *qkvBase, *attnBase, *whBase;
    cudaGetSymbolAddress((void**)&normHBase, g_norm_h);
    cudaGetSymbolAddress((void**)&qkvBase,   g_qkv_h);
    cudaGetSymbolAddress((void**)&attnBase,  g_attn_h);
    cudaGetSymbolAddress((void**)&whBase,    g_w_h);

    const size_t NCS  = (size_t)BATCH * CCH * SP;
    const size_t NQKV = (size_t)BATCH * 3 * CCH * SP;
    __half* normAh = normHBase;
    __half* normBh = normHBase + NCS;
    __half* qkvA   = qkvBase;
    __half* qkvB   = qkvBase + NQKV;
    __half* attnA  = attnBase;
    __half* attnB  = attnBase + NCS;
    __half* wqaH = whBase;
    __half* wqbH = whBase + 196608;
    __half* woaH = whBase + 393216;
    __half* wobH = whBase + 458752;

    // 1) GroupNorm (both branches) + weight conversion, one launch
    gn_w2h_kernel<<<768, 256>>>(
        x_A, x_B, gA, gB, bA, bB, normHBase,
        WqkvA, WqkvB, WoutA, WoutB, whBase);

    // 2) QKV projections, both branches (M = 768), BK=32, 3-stage
    dim3 gq(SP / 128, 768 / 128, 32);
    gemm16_kernel<1><<<gq, 256>>>(wqaH, wqbH, normAh, normBh,
                                  qkvA, qkvB, nullptr, nullptr,
                                  nullptr, nullptr, 768);

    // 3) Cross attention, both branches (256 queries per block)
    dim3 ga(2 * BATCH * NHEAD, SP / 256);
    attn16_kernel<<<ga, 256>>>(qkvA, qkvB, attnBase);

    // 4) Output projection + bias + fp16 residual, both branches (M = 256)
    dim3 go(SP / 128, 256 / 128, 32);
    gemm16_kernel<0><<<go, 256>>>(woaH, wobH, attnA, attnB,
                                  outp, outp + NCS, boutA, boutB,
                                  normAh, normBh, 256);
}